// round 13
// baseline (speedup 1.0000x reference)
#include <cuda_runtime.h>
#include <cuda_bf16.h>
#include <math.h>
#include <stdint.h>

// ---- problem constants ----
#define BB 16
#define CC 256
#define HH 96
#define WW 96
#define HWP (HH*WW)                 // 9216
#define NELEM (BB*CC*HWP)           // 37748736
#define S0 24
#define S1 48
#define S2 72
#define NCHUNK 4
#define BPC (BB/NCHUNK)             // 4 batches per pipeline chunk

// ---- scratch (device globals: allocation-free rule) ----
__device__ __nv_bfloat16 g_zh[NELEM];
__device__ __nv_bfloat16 g_zl[NELEM];
__device__ __nv_bfloat16 g_wh[CC*CC];
__device__ __nv_bfloat16 g_wl[CC*CC];
__device__ float g_dogk[CC*3];

// ===========================================================================
// PTX helpers
// ===========================================================================
__device__ __forceinline__ uint32_t smem_u32(const void* p) {
    uint32_t a;
    asm("{ .reg .u64 t; cvta.to.shared.u64 t, %1; cvt.u32.u64 %0, t; }"
        : "=r"(a) : "l"(p));
    return a;
}
#define CP16(dst, src) asm volatile( \
    "cp.async.cg.shared.global [%0], [%1], 16;" :: "r"(dst), "l"(src) : "memory")
#define CP_COMMIT() asm volatile("cp.async.commit_group;" ::: "memory")
#define CP_WAIT1() asm volatile("cp.async.wait_group 1;" ::: "memory")
#define CP_WAIT0() asm volatile("cp.async.wait_group 0;" ::: "memory")

__device__ __forceinline__ void ldsm_x4(uint32_t* r, uint32_t addr) {
    asm volatile("ldmatrix.sync.aligned.m8n8.x4.shared.b16 {%0,%1,%2,%3}, [%4];"
                 : "=r"(r[0]), "=r"(r[1]), "=r"(r[2]), "=r"(r[3]) : "r"(addr));
}
__device__ __forceinline__ void ldsm_x4_t(uint32_t* r, uint32_t addr) {
    asm volatile("ldmatrix.sync.aligned.m8n8.x4.trans.shared.b16 {%0,%1,%2,%3}, [%4];"
                 : "=r"(r[0]), "=r"(r[1]), "=r"(r[2]), "=r"(r[3]) : "r"(addr));
}
__device__ __forceinline__ void mma_bf16(float* c, const uint32_t* a, const uint32_t* b) {
    asm volatile(
        "mma.sync.aligned.m16n8k16.row.col.f32.bf16.bf16.f32 "
        "{%0,%1,%2,%3}, {%4,%5,%6,%7}, {%8,%9}, {%0,%1,%2,%3};"
        : "+f"(c[0]), "+f"(c[1]), "+f"(c[2]), "+f"(c[3])
        : "r"(a[0]), "r"(a[1]), "r"(a[2]), "r"(a[3]), "r"(b[0]), "r"(b[1]));
}

// ===========================================================================
// K0: per-channel DoG difference-kernel coefficients
// ===========================================================================
__global__ void k_params(const float* __restrict__ s1r, const float* __restrict__ s2r) {
    int c = threadIdx.x;
    float s1 = 2.f / (1.f + expf(-s1r[c]));
    float s2 = 2.f / (1.f + expf(-s2r[c]));
    float e1 = expf(-1.f / (2.f * s1 * s1)); float q1 = expf(-1.f / (s1 * s1));
    float e2 = expf(-1.f / (2.f * s2 * s2)); float q2 = expf(-1.f / (s2 * s2));
    float n1 = 1.f + 4.f * e1 + 4.f * q1;
    float n2 = 1.f + 4.f * e2 + 4.f * q2;
    g_dogk[c*3+0] = 1.f/n1 - 1.f/n2;
    g_dogk[c*3+1] = e1/n1 - e2/n2;
    g_dogk[c*3+2] = q1/n1 - q2/n2;
}

// K0b: split mixer weight into bf16 hi/lo
__global__ void k_wsplit(const float* __restrict__ w) {
    int i = blockIdx.x * 256 + threadIdx.x;
    float v = w[i];
    __nv_bfloat16 h = __float2bfloat16(v);
    g_wh[i] = h;
    g_wl[i] = __float2bfloat16(v - __bfloat162float(h));
}

// ===========================================================================
// edge_scale: upsample-edge for one scale over a 4-pixel strip (w%4==0).
// ===========================================================================
template<int S, int NT, int KSM, int XI0, int XI1, int XI2, int XI3>
__device__ __forceinline__ void edge_scale(
        const float* __restrict__ p, int h, int w, float scl,
        float wx0, float wx1, float wx2, float wx3,
        const float* __restrict__ yc, float* __restrict__ eout) {
    float fy = fmaxf((h + 0.5f) * scl - 0.5f, 0.f);
    int y0 = (int)fy;
    float wy = fy - (float)y0;
    const float* pr0 = p + y0 * S;
    const float* pr1 = p + min(y0 + 1, S - 1) * S;
    int x0 = (w >> 2) * KSM - 1;
    float T0[NT], T1[NT];
#pragma unroll
    for (int q = 0; q < NT; q++) {
        int cq = min(max(x0 + q, 0), S - 1);
        T0[q] = pr0[cq];
        T1[q] = pr1[cq];
    }
    const int xiv[4] = { XI0, XI1, XI2, XI3 };
    const float wxv[4] = { wx0, wx1, wx2, wx3 };
#pragma unroll
    for (int px = 0; px < 4; px++) {
        const int xi = xiv[px];
        float wx = wxv[px];
        float top = T0[xi] + (T0[xi+1] - T0[xi]) * wx;
        float bot = T1[xi] + (T1[xi+1] - T1[xi]) * wx;
        float up = top + (bot - top) * wy;
        eout[px] = fabsf(yc[px] - up);
    }
}

// ===========================================================================
// K1: fused per-plane elementwise chain. One CTA / (b,c) plane, 512 threads.
// ===========================================================================
#define SMF_Y  0
#define SMF_D0 9216
#define SMF_D1 (9216+576)
#define SMF_D2 (9216+2880)
#define PLANE_SMEM ((9216+8064)*4)   // 69120 B dynamic
#define PT 512

__global__ void __launch_bounds__(PT) k_plane(const float4* __restrict__ dec,
                                              const float4* __restrict__ skip,
                                              const float* __restrict__ wfea,
                                              int bcbase) {
    extern __shared__ float sm[];
    __shared__ int   s_di[144];
    __shared__ float s_dw[144];

    int bc = blockIdx.x + bcbase;
    int c  = bc % CC;
    int t  = threadIdx.x;

    if (t < 144) {
        int u = t;
        int s = (u < 24) ? 0 : (u < 72) ? 1 : 2;
        int o = (s == 0) ? u : (s == 1) ? u - 24 : u - 72;
        float sf = (s == 0) ? (96.f/S0) : (s == 1) ? (96.f/S1) : (96.f/S2);
        float f = fmaxf((o + 0.5f) * sf - 0.5f, 0.f);
        int i0 = (int)f;
        s_di[u] = i0;
        s_dw[u] = f - (float)i0;
    }

    const float4* dp = dec  + (size_t)bc * (HWP/4);
    const float4* sp = skip + (size_t)bc * (HWP/4);
    float4* y4 = (float4*)(sm + SMF_Y);
#pragma unroll
    for (int k = 0; k < 5; k++) {
        int i = k * PT + t;
        if (i < HWP/4) {
            float4 a = dp[i], b = sp[i];
            y4[i] = make_float4(a.x + b.x, a.y + b.y, a.z + b.z, a.w + b.w);
        }
    }
    __syncthreads();

    const float* sy = sm + SMF_Y;

#pragma unroll
    for (int k = 0; k < 16; k++) {
        int i = k * PT + t;
        if (i >= 8064) break;
        int S, off, o, tb;
        if (i < 576)       { S = S0; off = SMF_D0; o = i;        tb = 0;  }
        else if (i < 2880) { S = S1; off = SMF_D1; o = i - 576;  tb = 24; }
        else               { S = S2; off = SMF_D2; o = i - 2880; tb = 72; }
        int oy = o / S, ox = o % S;
        int y0 = s_di[tb + oy];  float wy = s_dw[tb + oy];
        int x0 = s_di[tb + ox];  float wx = s_dw[tb + ox];
        int r0 = y0 * WW, r1 = min(y0 + 1, HH - 1) * WW;
        int x1 = min(x0 + 1, WW - 1);
        float v00 = sy[r0 + x0], v01 = sy[r0 + x1];
        float v10 = sy[r1 + x0], v11 = sy[r1 + x1];
        sm[off + o] = (v00*(1.f-wx) + v01*wx)*(1.f-wy) + (v10*(1.f-wx) + v11*wx)*wy;
    }
    __syncthreads();

    float dC = g_dogk[c*3+0], dE = g_dogk[c*3+1], dX = g_dogk[c*3+2];
    float wf = wfea[c];
    const float* p0 = sm + SMF_D0;
    const float* p1 = sm + SMF_D1;
    const float* p2 = sm + SMF_D2;
    size_t gbase = (size_t)bc * HWP;
    uint2* zh4 = (uint2*)(g_zh + gbase);
    uint2* zl4 = (uint2*)(g_zl + gbase);

#pragma unroll
    for (int k = 0; k < 5; k++) {
        int j = k * PT + t;
        if (j < 2304) {
            int h = j / 24, w = 4 * (j % 24);

            float R[3][6];
            bool wl = w > 0, wr = w < WW - 4;
#pragma unroll
            for (int r = 0; r < 3; r++) {
                int hr = h - 1 + r;
                if (hr >= 0 && hr < HH) {
                    const float* rowp = sy + hr * WW;
                    float4 m = *(const float4*)(rowp + w);
                    R[r][1] = m.x; R[r][2] = m.y; R[r][3] = m.z; R[r][4] = m.w;
                    R[r][0] = wl ? rowp[w - 1] : 0.f;
                    R[r][5] = wr ? rowp[w + 4] : 0.f;
                } else {
#pragma unroll
                    for (int q = 0; q < 6; q++) R[r][q] = 0.f;
                }
            }
            float yc[4], dog[4];
#pragma unroll
            for (int px = 0; px < 4; px++) {
                yc[px] = R[1][px + 1];
                dog[px] = dC * R[1][px+1]
                        + dE * (R[0][px+1] + R[2][px+1] + R[1][px] + R[1][px+2])
                        + dX * (R[0][px] + R[0][px+2] + R[2][px] + R[2][px+2]);
            }

            float e0[4], e1[4], e2[4];
            edge_scale<S0, 3, 1, 0,0,1,1>(p0, h, w, 0.25f,
                0.625f, 0.875f, 0.125f, 0.375f, yc, e0);
            edge_scale<S1, 4, 2, 0,1,1,2>(p1, h, w, 0.5f,
                0.75f, 0.25f, 0.75f, 0.25f, yc, e1);
            edge_scale<S2, 5, 3, 0,1,2,3>(p2, h, w, 0.75f,
                0.875f, 0.625f, 0.375f, 0.125f, yc, e2);

            uint32_t hp[2], lp[2];
#pragma unroll
            for (int half = 0; half < 2; half++) {
                float v[2];
#pragma unroll
                for (int q = 0; q < 2; q++) {
                    int px = half * 2 + q;
                    float a01 = fabsf(e0[px] - e1[px]);
                    float a02 = fabsf(e0[px] - e2[px]);
                    float a12 = fabsf(e1[px] - e2[px]);
                    float we = (a01 + a02 + a12) * (1.f/3.f);
                    v[q] = 3.f*yc[px] + wf*we + dog[px];
                }
                __nv_bfloat16 h0 = __float2bfloat16(v[0]);
                __nv_bfloat16 h1 = __float2bfloat16(v[1]);
                __nv_bfloat16 l0 = __float2bfloat16(v[0] - __bfloat162float(h0));
                __nv_bfloat16 l1 = __float2bfloat16(v[1] - __bfloat162float(h1));
                hp[half] = ((uint32_t)__bfloat16_as_ushort(h1) << 16)
                         |  (uint32_t)__bfloat16_as_ushort(h0);
                lp[half] = ((uint32_t)__bfloat16_as_ushort(l1) << 16)
                         |  (uint32_t)__bfloat16_as_ushort(l0);
            }
            zh4[j] = make_uint2(hp[0], hp[1]);
            zl4[j] = make_uint2(lp[0], lp[1]);
        }
    }
}

// ===========================================================================
// K4: HMMA split-bf16 GEMM (exact R4/R6 config)
// ===========================================================================
#define ABUF_SZ 10240
#define BUF_STRIDE 36864            // 2*10240 + 2*8192
#define GEMM_SMEM (2*BUF_STRIDE)    // 73728

__global__ void __launch_bounds__(256, 2) k_gemm_mma(
        const float* __restrict__ skip, float* __restrict__ out, int bbase) {
    extern __shared__ char smem_raw[];
    uint32_t sb = smem_u32(smem_raw);

    int t = threadIdx.x, wid = t >> 5, lane = t & 31;
    int wm = wid & 1, wn = wid >> 1;
    int b = blockIdx.z + bbase, co0 = blockIdx.y * 128, n0 = blockIdx.x * 128;

    const __nv_bfloat16* whlo[2] = { g_wh, g_wl };
    const __nv_bfloat16* zhlo[2] = { g_zh, g_zl };

    auto load_chunk = [&](int kc, int d) {
        uint32_t base = sb + d * BUF_STRIDE;
#pragma unroll
        for (int j = 0; j < 4; j++) {            // A
            int idx = j * 256 + t;
            int hl = idx >> 9, rem = idx & 511;
            int row = rem >> 2, c = rem & 3;
            const __nv_bfloat16* src = whlo[hl] + (co0 + row) * CC + kc * 32 + c * 8;
            CP16(base + hl * ABUF_SZ + row * 80 + c * 16, src);
        }
#pragma unroll
        for (int j = 0; j < 4; j++) {            // B
            int idx = j * 256 + t;
            int hl = idx >> 9, rem = idx & 511;
            int row = rem >> 4, c = rem & 15;
            const __nv_bfloat16* src = zhlo[hl]
                + (size_t)(b * CC + kc * 32 + row) * HWP + n0 + c * 8;
            CP16(base + 2 * ABUF_SZ + hl * 8192 + row * 256
                 + (uint32_t)((c ^ (row & 7)) << 4), src);
        }
    };

    float acc[4][4][4];
#pragma unroll
    for (int i = 0; i < 4; i++)
#pragma unroll
        for (int j = 0; j < 4; j++)
#pragma unroll
            for (int k = 0; k < 4; k++) acc[i][j][k] = 0.f;

    int lt = lane >> 3;
    int lrA = (lane & 7) + ((lt & 1) << 3);
    int lcA = (lt >> 1) << 4;
    int lkB = (lane & 7) + ((lt & 1) << 3);
    int lnB = (lt >> 1) << 3;

    load_chunk(0, 0);
    CP_COMMIT();

    for (int kc = 0; kc < 8; kc++) {
        int d = kc & 1;
        if (kc + 1 < 8) { load_chunk(kc + 1, d ^ 1); CP_COMMIT(); CP_WAIT1(); }
        else           { CP_WAIT0(); }
        __syncthreads();

        uint32_t abase = sb + d * BUF_STRIDE;
        uint32_t bb2 = abase + 2 * ABUF_SZ;

#pragma unroll
        for (int ks = 0; ks < 2; ks++) {
            uint32_t ah[4][4], al[4][4];
#pragma unroll
            for (int mi = 0; mi < 4; mi++) {
                uint32_t arow = (uint32_t)(wm * 64 + mi * 16 + lrA);
                ldsm_x4(ah[mi], abase + arow * 80 + ks * 32 + lcA);
                ldsm_x4(al[mi], abase + ABUF_SZ + arow * 80 + ks * 32 + lcA);
            }
#pragma unroll
            for (int np = 0; np < 2; np++) {
                uint32_t krow = (uint32_t)(ks * 16 + lkB);
                uint32_t nb   = (uint32_t)(wn * 32 + np * 16 + lnB);
                uint32_t chunk = nb >> 3;
                uint32_t swz = (chunk ^ (krow & 7)) << 4;
                uint32_t bh[4], bl[4];
                ldsm_x4_t(bh, bb2 + krow * 256 + swz);
                ldsm_x4_t(bl, bb2 + 8192 + krow * 256 + swz);
#pragma unroll
                for (int mi = 0; mi < 4; mi++) {
                    mma_bf16(acc[mi][np*2+0], ah[mi], bh + 0);
                    mma_bf16(acc[mi][np*2+1], ah[mi], bh + 2);
                    mma_bf16(acc[mi][np*2+0], ah[mi], bl + 0);
                    mma_bf16(acc[mi][np*2+1], ah[mi], bl + 2);
                    mma_bf16(acc[mi][np*2+0], al[mi], bh + 0);
                    mma_bf16(acc[mi][np*2+1], al[mi], bh + 2);
                }
            }
        }
        __syncthreads();
    }

    int er = lane >> 2, ec = (lane & 3) * 2;
#pragma unroll
    for (int mi = 0; mi < 4; mi++) {
#pragma unroll
        for (int ni = 0; ni < 4; ni++) {
            int row = co0 + wm * 64 + mi * 16 + er;
            int col = n0 + wn * 32 + ni * 8 + ec;
            size_t g0 = (size_t)(b * CC + row) * HWP + col;
            size_t g1 = g0 + 8 * HWP;
            float2 s0 = *(const float2*)(skip + g0);
            float2 s1 = *(const float2*)(skip + g1);
            float2 o0 = make_float2(acc[mi][ni][0] + s0.x, acc[mi][ni][1] + s0.y);
            float2 o1 = make_float2(acc[mi][ni][2] + s1.x, acc[mi][ni][3] + s1.y);
            *(float2*)(out + g0) = o0;
            *(float2*)(out + g1) = o1;
        }
    }
}

// ===========================================================================
// Launch: planes on s2, gemms on s3 (both non-blocking) so the captured DAG
// has ONLY the intended plane_i -> gemm_i edges. Legacy stream 0 carries the
// fork (setup) and the final join. Fixes R12's implicit legacy-stream
// serialization (gemm on stream 0 picked up deps on ALL enqueued planes).
// ===========================================================================
extern "C" void kernel_launch(void* const* d_in, const int* in_sizes, int n_in,
                              void* d_out, int out_size) {
    const float* skip   = (const float*)d_in[0];
    const float* dec    = (const float*)d_in[1];
    const float* w_fea  = (const float*)d_in[2];
    const float* sigma1 = (const float*)d_in[3];
    const float* sigma2 = (const float*)d_in[4];
    const float* mixerw = (const float*)d_in[5];
    float* out = (float*)d_out;

    static cudaStream_t s2 = nullptr, s3 = nullptr;
    static cudaEvent_t evF = nullptr, evG = nullptr, evP[NCHUNK];
    static bool attr_done = false;
    if (s2 == nullptr) {
        cudaStreamCreateWithFlags(&s2, cudaStreamNonBlocking);
        cudaStreamCreateWithFlags(&s3, cudaStreamNonBlocking);
        cudaEventCreateWithFlags(&evF, cudaEventDisableTiming);
        cudaEventCreateWithFlags(&evG, cudaEventDisableTiming);
        for (int i = 0; i < NCHUNK; i++)
            cudaEventCreateWithFlags(&evP[i], cudaEventDisableTiming);
    }
    if (!attr_done) {
        cudaFuncSetAttribute(k_plane, cudaFuncAttributeMaxDynamicSharedMemorySize,
                             PLANE_SMEM);
        cudaFuncSetAttribute(k_gemm_mma, cudaFuncAttributeMaxDynamicSharedMemorySize,
                             GEMM_SMEM);
        attr_done = true;
    }

    // setup on stream 0 (fork point)
    k_params<<<1, CC>>>(sigma1, sigma2);
    k_wsplit<<<CC*CC/256, 256>>>(mixerw);
    cudaEventRecord(evF, 0);

    // planes on s2
    cudaStreamWaitEvent(s2, evF, 0);
    for (int i = 0; i < NCHUNK; i++) {
        k_plane<<<BPC*CC, PT, PLANE_SMEM, s2>>>((const float4*)dec,
                                                (const float4*)skip, w_fea,
                                                i * BPC * CC);
        cudaEventRecord(evP[i], s2);
    }

    // gemms on s3, each gated only on its own plane chunk
    cudaStreamWaitEvent(s3, evF, 0);
    dim3 grid(HWP / 128, CC / 128, BPC);
    for (int i = 0; i < NCHUNK; i++) {
        cudaStreamWaitEvent(s3, evP[i], 0);
        k_gemm_mma<<<grid, 256, GEMM_SMEM, s3>>>(skip, out, i * BPC);
    }
    cudaEventRecord(evG, s3);

    // join back to stream 0
    cudaStreamWaitEvent(0, evG, 0);
}

// round 14
// speedup vs baseline: 1.1615x; 1.1615x over previous
#include <cuda_runtime.h>
#include <cuda_bf16.h>
#include <math.h>
#include <stdint.h>

// ---- problem constants ----
#define BB 16
#define CC 256
#define HH 96
#define WW 96
#define HWP (HH*WW)                 // 9216
#define NELEM (BB*CC*HWP)           // 37748736
#define S0 24
#define S1 48
#define S2 72

// ---- scratch (device globals: allocation-free rule) ----
__device__ __nv_bfloat16 g_zh[NELEM];
__device__ __nv_bfloat16 g_zl[NELEM];
__device__ __nv_bfloat16 g_wh[CC*CC];
__device__ __nv_bfloat16 g_wl[CC*CC];
__device__ float g_dogk[CC*3];

// ===========================================================================
// PTX helpers
// ===========================================================================
__device__ __forceinline__ uint32_t smem_u32(const void* p) {
    uint32_t a;
    asm("{ .reg .u64 t; cvta.to.shared.u64 t, %1; cvt.u32.u64 %0, t; }"
        : "=r"(a) : "l"(p));
    return a;
}
#define CP16(dst, src) asm volatile( \
    "cp.async.cg.shared.global [%0], [%1], 16;" :: "r"(dst), "l"(src) : "memory")
#define CP_COMMIT() asm volatile("cp.async.commit_group;" ::: "memory")
#define CP_WAIT1() asm volatile("cp.async.wait_group 1;" ::: "memory")
#define CP_WAIT0() asm volatile("cp.async.wait_group 0;" ::: "memory")

__device__ __forceinline__ void ldsm_x4(uint32_t* r, uint32_t addr) {
    asm volatile("ldmatrix.sync.aligned.m8n8.x4.shared.b16 {%0,%1,%2,%3}, [%4];"
                 : "=r"(r[0]), "=r"(r[1]), "=r"(r[2]), "=r"(r[3]) : "r"(addr));
}
__device__ __forceinline__ void ldsm_x4_t(uint32_t* r, uint32_t addr) {
    asm volatile("ldmatrix.sync.aligned.m8n8.x4.trans.shared.b16 {%0,%1,%2,%3}, [%4];"
                 : "=r"(r[0]), "=r"(r[1]), "=r"(r[2]), "=r"(r[3]) : "r"(addr));
}
__device__ __forceinline__ void mma_bf16(float* c, const uint32_t* a, const uint32_t* b) {
    asm volatile(
        "mma.sync.aligned.m16n8k16.row.col.f32.bf16.bf16.f32 "
        "{%0,%1,%2,%3}, {%4,%5,%6,%7}, {%8,%9}, {%0,%1,%2,%3};"
        : "+f"(c[0]), "+f"(c[1]), "+f"(c[2]), "+f"(c[3])
        : "r"(a[0]), "r"(a[1]), "r"(a[2]), "r"(a[3]), "r"(b[0]), "r"(b[1]));
}

// ===========================================================================
// K0: per-channel DoG difference-kernel coefficients
// ===========================================================================
__global__ void k_params(const float* __restrict__ s1r, const float* __restrict__ s2r) {
    int c = threadIdx.x;
    float s1 = 2.f / (1.f + expf(-s1r[c]));
    float s2 = 2.f / (1.f + expf(-s2r[c]));
    float e1 = expf(-1.f / (2.f * s1 * s1)); float q1 = expf(-1.f / (s1 * s1));
    float e2 = expf(-1.f / (2.f * s2 * s2)); float q2 = expf(-1.f / (s2 * s2));
    float n1 = 1.f + 4.f * e1 + 4.f * q1;
    float n2 = 1.f + 4.f * e2 + 4.f * q2;
    g_dogk[c*3+0] = 1.f/n1 - 1.f/n2;
    g_dogk[c*3+1] = e1/n1 - e2/n2;
    g_dogk[c*3+2] = q1/n1 - q2/n2;
}

// K0b: split mixer weight into bf16 hi/lo
__global__ void k_wsplit(const float* __restrict__ w) {
    int i = blockIdx.x * 256 + threadIdx.x;
    float v = w[i];
    __nv_bfloat16 h = __float2bfloat16(v);
    g_wh[i] = h;
    g_wl[i] = __float2bfloat16(v - __bfloat162float(h));
}

// ===========================================================================
// edge_scale: upsample-edge for one scale over a 4-pixel strip (w%4==0).
// ===========================================================================
template<int S, int NT, int KSM, int XI0, int XI1, int XI2, int XI3>
__device__ __forceinline__ void edge_scale(
        const float* __restrict__ p, int h, int w, float scl,
        float wx0, float wx1, float wx2, float wx3,
        const float* __restrict__ yc, float* __restrict__ eout) {
    float fy = fmaxf((h + 0.5f) * scl - 0.5f, 0.f);
    int y0 = (int)fy;
    float wy = fy - (float)y0;
    const float* pr0 = p + y0 * S;
    const float* pr1 = p + min(y0 + 1, S - 1) * S;
    int x0 = (w >> 2) * KSM - 1;
    float T0[NT], T1[NT];
#pragma unroll
    for (int q = 0; q < NT; q++) {
        int cq = min(max(x0 + q, 0), S - 1);
        T0[q] = pr0[cq];
        T1[q] = pr1[cq];
    }
    const int xiv[4] = { XI0, XI1, XI2, XI3 };
    const float wxv[4] = { wx0, wx1, wx2, wx3 };
#pragma unroll
    for (int px = 0; px < 4; px++) {
        const int xi = xiv[px];
        float wx = wxv[px];
        float top = T0[xi] + (T0[xi+1] - T0[xi]) * wx;
        float bot = T1[xi] + (T1[xi+1] - T1[xi]) * wx;
        float up = top + (bot - top) * wy;
        eout[px] = fabsf(yc[px] - up);
    }
}

// ===========================================================================
// K1: fused per-plane elementwise chain. One CTA / (b,c) plane, 512 threads.
//   Phase 2 uses exact compile-time downsample geometry (no coord tables):
//     S0 (x4):   i0 = 4o+1, w = 1/2
//     S1 (x2):   i0 = 2o,   w = 1/2
//     S2 (x4/3): i0 = 4*(o/3)+(o%3), w = {1/6, 1/2, 5/6}[o%3]
// ===========================================================================
#define SMF_Y  0
#define SMF_D0 9216
#define SMF_D1 (9216+576)
#define SMF_D2 (9216+2880)
#define PLANE_SMEM ((9216+8064)*4)   // 69120 B dynamic
#define PT 512

__device__ __forceinline__ void ds_coord_s2(int o, int& i0, float& w) {
    int m = o / 3, r = o - 3 * m;
    i0 = 4 * m + r;
    w = (r == 0) ? (1.f/6.f) : (r == 1) ? 0.5f : (5.f/6.f);
}

__global__ void __launch_bounds__(PT) k_plane(const float4* __restrict__ dec,
                                              const float4* __restrict__ skip,
                                              const float* __restrict__ wfea) {
    extern __shared__ float sm[];
    int bc = blockIdx.x;
    int c  = bc % CC;
    int t  = threadIdx.x;

    // 1) y = dec + skip into smem
    const float4* dp = dec  + (size_t)bc * (HWP/4);
    const float4* sp = skip + (size_t)bc * (HWP/4);
    float4* y4 = (float4*)(sm + SMF_Y);
#pragma unroll
    for (int k = 0; k < 5; k++) {
        int i = k * PT + t;
        if (i < HWP/4) {
            float4 a = dp[i], b = sp[i];
            y4[i] = make_float4(a.x + b.x, a.y + b.y, a.z + b.z, a.w + b.w);
        }
    }
    __syncthreads();

    const float* sy = sm + SMF_Y;

    // 2) three bilinear downsamples into smem (8064 outputs), exact geometry
#pragma unroll
    for (int k = 0; k < 16; k++) {
        int i = k * PT + t;
        if (i >= 8064) break;
        int y0, x0; float wy, wx;
        int off, o, S;
        if (i < 576) {
            S = S0; off = SMF_D0; o = i;
            int oy = o / S0, ox = o - oy * S0;
            y0 = 4 * oy + 1; x0 = 4 * ox + 1; wy = 0.5f; wx = 0.5f;
        } else if (i < 2880) {
            S = S1; off = SMF_D1; o = i - 576;
            int oy = o / S1, ox = o - oy * S1;
            y0 = 2 * oy; x0 = 2 * ox; wy = 0.5f; wx = 0.5f;
        } else {
            S = S2; off = SMF_D2; o = i - 2880;
            int oy = o / S2, ox = o - oy * S2;
            ds_coord_s2(oy, y0, wy);
            ds_coord_s2(ox, x0, wx);
        }
        const float* r0p = sy + y0 * WW;
        const float* r1p = sy + (y0 + 1) * WW;   // never clamps (max y0 = 94)
        float v00 = r0p[x0], v01 = r0p[x0 + 1];
        float v10 = r1p[x0], v11 = r1p[x0 + 1];
        sm[off + o] = (v00*(1.f-wx) + v01*wx)*(1.f-wy) + (v10*(1.f-wx) + v11*wx)*wy;
    }
    __syncthreads();

    // 3) fused edges + DoG + combine -> zh/zl: 4-pixel strips
    float dC = g_dogk[c*3+0], dE = g_dogk[c*3+1], dX = g_dogk[c*3+2];
    float wf = wfea[c];
    const float* p0 = sm + SMF_D0;
    const float* p1 = sm + SMF_D1;
    const float* p2 = sm + SMF_D2;
    size_t gbase = (size_t)bc * HWP;
    uint2* zh4 = (uint2*)(g_zh + gbase);
    uint2* zl4 = (uint2*)(g_zl + gbase);

#pragma unroll
    for (int k = 0; k < 5; k++) {
        int j = k * PT + t;                 // strip index 0..2303 (24 per row)
        if (j < 2304) {
            int h = j / 24, w = 4 * (j % 24);

            float R[3][6];
            bool wl = w > 0, wr = w < WW - 4;
#pragma unroll
            for (int r = 0; r < 3; r++) {
                int hr = h - 1 + r;
                if (hr >= 0 && hr < HH) {
                    const float* rowp = sy + hr * WW;
                    float4 m = *(const float4*)(rowp + w);
                    R[r][1] = m.x; R[r][2] = m.y; R[r][3] = m.z; R[r][4] = m.w;
                    R[r][0] = wl ? rowp[w - 1] : 0.f;
                    R[r][5] = wr ? rowp[w + 4] : 0.f;
                } else {
#pragma unroll
                    for (int q = 0; q < 6; q++) R[r][q] = 0.f;
                }
            }
            float yc[4], dog[4];
#pragma unroll
            for (int px = 0; px < 4; px++) {
                yc[px] = R[1][px + 1];
                dog[px] = dC * R[1][px+1]
                        + dE * (R[0][px+1] + R[2][px+1] + R[1][px] + R[1][px+2])
                        + dX * (R[0][px] + R[0][px+2] + R[2][px] + R[2][px+2]);
            }

            float e0[4], e1[4], e2[4];
            edge_scale<S0, 3, 1, 0,0,1,1>(p0, h, w, 0.25f,
                0.625f, 0.875f, 0.125f, 0.375f, yc, e0);
            edge_scale<S1, 4, 2, 0,1,1,2>(p1, h, w, 0.5f,
                0.75f, 0.25f, 0.75f, 0.25f, yc, e1);
            edge_scale<S2, 5, 3, 0,1,2,3>(p2, h, w, 0.75f,
                0.875f, 0.625f, 0.375f, 0.125f, yc, e2);

            uint32_t hp[2], lp[2];
#pragma unroll
            for (int half = 0; half < 2; half++) {
                float v[2];
#pragma unroll
                for (int q = 0; q < 2; q++) {
                    int px = half * 2 + q;
                    float a01 = fabsf(e0[px] - e1[px]);
                    float a02 = fabsf(e0[px] - e2[px]);
                    float a12 = fabsf(e1[px] - e2[px]);
                    float we = (a01 + a02 + a12) * (1.f/3.f);
                    v[q] = 3.f*yc[px] + wf*we + dog[px];
                }
                __nv_bfloat16 h0 = __float2bfloat16(v[0]);
                __nv_bfloat16 h1 = __float2bfloat16(v[1]);
                __nv_bfloat16 l0 = __float2bfloat16(v[0] - __bfloat162float(h0));
                __nv_bfloat16 l1 = __float2bfloat16(v[1] - __bfloat162float(h1));
                hp[half] = ((uint32_t)__bfloat16_as_ushort(h1) << 16)
                         |  (uint32_t)__bfloat16_as_ushort(h0);
                lp[half] = ((uint32_t)__bfloat16_as_ushort(l1) << 16)
                         |  (uint32_t)__bfloat16_as_ushort(l0);
            }
            zh4[j] = make_uint2(hp[0], hp[1]);
            zl4[j] = make_uint2(lp[0], lp[1]);
        }
    }
}

// ===========================================================================
// K4: HMMA split-bf16 GEMM (exact R4/R6/R11 config, measured ~174-176us)
// ===========================================================================
#define ABUF_SZ 10240
#define BUF_STRIDE 36864            // 2*10240 + 2*8192
#define GEMM_SMEM (2*BUF_STRIDE)    // 73728

__global__ void __launch_bounds__(256, 2) k_gemm_mma(
        const float* __restrict__ skip, float* __restrict__ out) {
    extern __shared__ char smem_raw[];
    uint32_t sb = smem_u32(smem_raw);

    int t = threadIdx.x, wid = t >> 5, lane = t & 31;
    int wm = wid & 1, wn = wid >> 1;
    int b = blockIdx.z, co0 = blockIdx.y * 128, n0 = blockIdx.x * 128;

    const __nv_bfloat16* whlo[2] = { g_wh, g_wl };
    const __nv_bfloat16* zhlo[2] = { g_zh, g_zl };

    auto load_chunk = [&](int kc, int d) {
        uint32_t base = sb + d * BUF_STRIDE;
#pragma unroll
        for (int j = 0; j < 4; j++) {            // A
            int idx = j * 256 + t;
            int hl = idx >> 9, rem = idx & 511;
            int row = rem >> 2, c = rem & 3;
            const __nv_bfloat16* src = whlo[hl] + (co0 + row) * CC + kc * 32 + c * 8;
            CP16(base + hl * ABUF_SZ + row * 80 + c * 16, src);
        }
#pragma unroll
        for (int j = 0; j < 4; j++) {            // B
            int idx = j * 256 + t;
            int hl = idx >> 9, rem = idx & 511;
            int row = rem >> 4, c = rem & 15;
            const __nv_bfloat16* src = zhlo[hl]
                + (size_t)(b * CC + kc * 32 + row) * HWP + n0 + c * 8;
            CP16(base + 2 * ABUF_SZ + hl * 8192 + row * 256
                 + (uint32_t)((c ^ (row & 7)) << 4), src);
        }
    };

    float acc[4][4][4];
#pragma unroll
    for (int i = 0; i < 4; i++)
#pragma unroll
        for (int j = 0; j < 4; j++)
#pragma unroll
            for (int k = 0; k < 4; k++) acc[i][j][k] = 0.f;

    int lt = lane >> 3;
    int lrA = (lane & 7) + ((lt & 1) << 3);
    int lcA = (lt >> 1) << 4;
    int lkB = (lane & 7) + ((lt & 1) << 3);
    int lnB = (lt >> 1) << 3;

    load_chunk(0, 0);
    CP_COMMIT();

    for (int kc = 0; kc < 8; kc++) {
        int d = kc & 1;
        if (kc + 1 < 8) { load_chunk(kc + 1, d ^ 1); CP_COMMIT(); CP_WAIT1(); }
        else           { CP_WAIT0(); }
        __syncthreads();

        uint32_t abase = sb + d * BUF_STRIDE;
        uint32_t bb2 = abase + 2 * ABUF_SZ;

#pragma unroll
        for (int ks = 0; ks < 2; ks++) {
            uint32_t ah[4][4], al[4][4];
#pragma unroll
            for (int mi = 0; mi < 4; mi++) {
                uint32_t arow = (uint32_t)(wm * 64 + mi * 16 + lrA);
                ldsm_x4(ah[mi], abase + arow * 80 + ks * 32 + lcA);
                ldsm_x4(al[mi], abase + ABUF_SZ + arow * 80 + ks * 32 + lcA);
            }
#pragma unroll
            for (int np = 0; np < 2; np++) {
                uint32_t krow = (uint32_t)(ks * 16 + lkB);
                uint32_t nb   = (uint32_t)(wn * 32 + np * 16 + lnB);
                uint32_t chunk = nb >> 3;
                uint32_t swz = (chunk ^ (krow & 7)) << 4;
                uint32_t bh[4], bl[4];
                ldsm_x4_t(bh, bb2 + krow * 256 + swz);
                ldsm_x4_t(bl, bb2 + 8192 + krow * 256 + swz);
#pragma unroll
                for (int mi = 0; mi < 4; mi++) {
                    mma_bf16(acc[mi][np*2+0], ah[mi], bh + 0);
                    mma_bf16(acc[mi][np*2+1], ah[mi], bh + 2);
                    mma_bf16(acc[mi][np*2+0], ah[mi], bl + 0);
                    mma_bf16(acc[mi][np*2+1], ah[mi], bl + 2);
                    mma_bf16(acc[mi][np*2+0], al[mi], bh + 0);
                    mma_bf16(acc[mi][np*2+1], al[mi], bh + 2);
                }
            }
        }
        __syncthreads();
    }

    int er = lane >> 2, ec = (lane & 3) * 2;
#pragma unroll
    for (int mi = 0; mi < 4; mi++) {
#pragma unroll
        for (int ni = 0; ni < 4; ni++) {
            int row = co0 + wm * 64 + mi * 16 + er;
            int col = n0 + wn * 32 + ni * 8 + ec;
            size_t g0 = (size_t)(b * CC + row) * HWP + col;
            size_t g1 = g0 + 8 * HWP;
            float2 s0 = *(const float2*)(skip + g0);
            float2 s1 = *(const float2*)(skip + g1);
            float2 o0 = make_float2(acc[mi][ni][0] + s0.x, acc[mi][ni][1] + s0.y);
            float2 o1 = make_float2(acc[mi][ni][2] + s1.x, acc[mi][ni][3] + s1.y);
            *(float2*)(out + g0) = o0;
            *(float2*)(out + g1) = o1;
        }
    }
}

// ===========================================================================
// Launch: sequential (R11 structure — overlap experiments R12/R13 regressed)
// ===========================================================================
extern "C" void kernel_launch(void* const* d_in, const int* in_sizes, int n_in,
                              void* d_out, int out_size) {
    const float* skip   = (const float*)d_in[0];
    const float* dec    = (const float*)d_in[1];
    const float* w_fea  = (const float*)d_in[2];
    const float* sigma1 = (const float*)d_in[3];
    const float* sigma2 = (const float*)d_in[4];
    const float* mixerw = (const float*)d_in[5];
    float* out = (float*)d_out;

    k_params<<<1, CC>>>(sigma1, sigma2);
    k_wsplit<<<CC*CC/256, 256>>>(mixerw);

    cudaFuncSetAttribute(k_plane, cudaFuncAttributeMaxDynamicSharedMemorySize,
                         PLANE_SMEM);
    k_plane<<<BB*CC, PT, PLANE_SMEM>>>((const float4*)dec, (const float4*)skip,
                                       w_fea);

    cudaFuncSetAttribute(k_gemm_mma, cudaFuncAttributeMaxDynamicSharedMemorySize,
                         GEMM_SMEM);
    dim3 grid(HWP / 128, CC / 128, BB);
    k_gemm_mma<<<grid, 256, GEMM_SMEM>>>(skip, out);
}

// round 15
// speedup vs baseline: 1.3643x; 1.1746x over previous
#include <cuda_runtime.h>
#include <cuda_fp16.h>
#include <math.h>
#include <stdint.h>

// ---- problem constants ----
#define BB 16
#define CC 256
#define HH 96
#define WW 96
#define HWP (HH*WW)                 // 9216
#define NELEM (BB*CC*HWP)           // 37748736
#define S0 24
#define S1 48
#define S2 72

// ---- scratch (device globals: allocation-free rule) ----
__device__ __half g_zq[NELEM];       // z quantized to fp16
__device__ __half g_wh[CC*CC];       // fp16(16*W) hi
__device__ __half g_wl[CC*CC];       // fp16(16*W - hi) lo

// ===========================================================================
// PTX helpers
// ===========================================================================
__device__ __forceinline__ uint32_t smem_u32(const void* p) {
    uint32_t a;
    asm("{ .reg .u64 t; cvta.to.shared.u64 t, %1; cvt.u32.u64 %0, t; }"
        : "=r"(a) : "l"(p));
    return a;
}
#define CP16(dst, src) asm volatile( \
    "cp.async.cg.shared.global [%0], [%1], 16;" :: "r"(dst), "l"(src) : "memory")
#define CP_COMMIT() asm volatile("cp.async.commit_group;" ::: "memory")
#define CP_WAIT1() asm volatile("cp.async.wait_group 1;" ::: "memory")
#define CP_WAIT0() asm volatile("cp.async.wait_group 0;" ::: "memory")

__device__ __forceinline__ void ldsm_x4(uint32_t* r, uint32_t addr) {
    asm volatile("ldmatrix.sync.aligned.m8n8.x4.shared.b16 {%0,%1,%2,%3}, [%4];"
                 : "=r"(r[0]), "=r"(r[1]), "=r"(r[2]), "=r"(r[3]) : "r"(addr));
}
__device__ __forceinline__ void ldsm_x4_t(uint32_t* r, uint32_t addr) {
    asm volatile("ldmatrix.sync.aligned.m8n8.x4.trans.shared.b16 {%0,%1,%2,%3}, [%4];"
                 : "=r"(r[0]), "=r"(r[1]), "=r"(r[2]), "=r"(r[3]) : "r"(addr));
}
__device__ __forceinline__ void mma_fp16(float* c, const uint32_t* a, const uint32_t* b) {
    asm volatile(
        "mma.sync.aligned.m16n8k16.row.col.f32.f16.f16.f32 "
        "{%0,%1,%2,%3}, {%4,%5,%6,%7}, {%8,%9}, {%0,%1,%2,%3};"
        : "+f"(c[0]), "+f"(c[1]), "+f"(c[2]), "+f"(c[3])
        : "r"(a[0]), "r"(a[1]), "r"(a[2]), "r"(a[3]), "r"(b[0]), "r"(b[1]));
}

// ===========================================================================
// K0: split (16*W) into fp16 hi/lo  (x16 keeps lo in normal fp16 range;
//     epilogue multiplies by 1/16 — exact power-of-2, no precision loss)
// ===========================================================================
__global__ void k_wsplit(const float* __restrict__ w) {
    int i = blockIdx.x * 256 + threadIdx.x;
    float v = 16.f * w[i];
    __half h = __float2half_rn(v);
    g_wh[i] = h;
    g_wl[i] = __float2half_rn(v - __half2float(h));
}

// ===========================================================================
// edge_scale: upsample-edge for one scale over a 4-pixel strip (w%4==0).
// ===========================================================================
template<int S, int NT, int KSM, int XI0, int XI1, int XI2, int XI3>
__device__ __forceinline__ void edge_scale(
        const float* __restrict__ p, int h, int w, float scl,
        float wx0, float wx1, float wx2, float wx3,
        const float* __restrict__ yc, float* __restrict__ eout) {
    float fy = fmaxf((h + 0.5f) * scl - 0.5f, 0.f);
    int y0 = (int)fy;
    float wy = fy - (float)y0;
    const float* pr0 = p + y0 * S;
    const float* pr1 = p + min(y0 + 1, S - 1) * S;
    int x0 = (w >> 2) * KSM - 1;
    float T0[NT], T1[NT];
#pragma unroll
    for (int q = 0; q < NT; q++) {
        int cq = min(max(x0 + q, 0), S - 1);
        T0[q] = pr0[cq];
        T1[q] = pr1[cq];
    }
    const int xiv[4] = { XI0, XI1, XI2, XI3 };
    const float wxv[4] = { wx0, wx1, wx2, wx3 };
#pragma unroll
    for (int px = 0; px < 4; px++) {
        const int xi = xiv[px];
        float wx = wxv[px];
        float top = T0[xi] + (T0[xi+1] - T0[xi]) * wx;
        float bot = T1[xi] + (T1[xi+1] - T1[xi]) * wx;
        float up = top + (bot - top) * wy;
        eout[px] = fabsf(yc[px] - up);
    }
}

// ===========================================================================
// K1: fused per-plane elementwise chain. One CTA / (b,c) plane, 512 threads.
//   DoG coefficients computed in-kernel (k_params folded in).
//   Output: z quantized to fp16 (single array).
// ===========================================================================
#define SMF_Y  0
#define SMF_D0 9216
#define SMF_D1 (9216+576)
#define SMF_D2 (9216+2880)
#define PLANE_SMEM ((9216+8064)*4)   // 69120 B dynamic
#define PT 512

__device__ __forceinline__ void ds_coord_s2(int o, int& i0, float& w) {
    int m = o / 3, r = o - 3 * m;
    i0 = 4 * m + r;
    w = (r == 0) ? (1.f/6.f) : (r == 1) ? 0.5f : (5.f/6.f);
}

__global__ void __launch_bounds__(PT) k_plane(const float4* __restrict__ dec,
                                              const float4* __restrict__ skip,
                                              const float* __restrict__ wfea,
                                              const float* __restrict__ s1r,
                                              const float* __restrict__ s2r) {
    extern __shared__ float sm[];
    __shared__ float s_dog[3];

    int bc = blockIdx.x;
    int c  = bc % CC;
    int t  = threadIdx.x;

    // 0) DoG difference-kernel coefficients for this channel
    if (t == 0) {
        float s1 = 2.f / (1.f + expf(-s1r[c]));
        float s2 = 2.f / (1.f + expf(-s2r[c]));
        float e1 = expf(-1.f / (2.f * s1 * s1)); float q1 = expf(-1.f / (s1 * s1));
        float e2 = expf(-1.f / (2.f * s2 * s2)); float q2 = expf(-1.f / (s2 * s2));
        float n1 = 1.f + 4.f * e1 + 4.f * q1;
        float n2 = 1.f + 4.f * e2 + 4.f * q2;
        s_dog[0] = 1.f/n1 - 1.f/n2;
        s_dog[1] = e1/n1 - e2/n2;
        s_dog[2] = q1/n1 - q2/n2;
    }

    // 1) y = dec + skip into smem
    const float4* dp = dec  + (size_t)bc * (HWP/4);
    const float4* sp = skip + (size_t)bc * (HWP/4);
    float4* y4 = (float4*)(sm + SMF_Y);
#pragma unroll
    for (int k = 0; k < 5; k++) {
        int i = k * PT + t;
        if (i < HWP/4) {
            float4 a = dp[i], b = sp[i];
            y4[i] = make_float4(a.x + b.x, a.y + b.y, a.z + b.z, a.w + b.w);
        }
    }
    __syncthreads();

    const float* sy = sm + SMF_Y;

    // 2) three bilinear downsamples into smem, exact compile-time geometry
#pragma unroll
    for (int k = 0; k < 16; k++) {
        int i = k * PT + t;
        if (i >= 8064) break;
        int y0, x0; float wy, wx;
        int off, o;
        if (i < 576) {
            off = SMF_D0; o = i;
            int oy = o / S0, ox = o - oy * S0;
            y0 = 4 * oy + 1; x0 = 4 * ox + 1; wy = 0.5f; wx = 0.5f;
        } else if (i < 2880) {
            off = SMF_D1; o = i - 576;
            int oy = o / S1, ox = o - oy * S1;
            y0 = 2 * oy; x0 = 2 * ox; wy = 0.5f; wx = 0.5f;
        } else {
            off = SMF_D2; o = i - 2880;
            int oy = o / S2, ox = o - oy * S2;
            ds_coord_s2(oy, y0, wy);
            ds_coord_s2(ox, x0, wx);
        }
        const float* r0p = sy + y0 * WW;
        const float* r1p = sy + (y0 + 1) * WW;   // never clamps (max y0 = 94)
        float v00 = r0p[x0], v01 = r0p[x0 + 1];
        float v10 = r1p[x0], v11 = r1p[x0 + 1];
        sm[off + o] = (v00*(1.f-wx) + v01*wx)*(1.f-wy) + (v10*(1.f-wx) + v11*wx)*wy;
    }
    __syncthreads();

    // 3) fused edges + DoG + combine -> zq (fp16): 4-pixel strips
    float dC = s_dog[0], dE = s_dog[1], dX = s_dog[2];
    float wf = wfea[c];
    const float* p0 = sm + SMF_D0;
    const float* p1 = sm + SMF_D1;
    const float* p2 = sm + SMF_D2;
    size_t gbase = (size_t)bc * HWP;
    uint2* zq4 = (uint2*)(g_zq + gbase);

#pragma unroll
    for (int k = 0; k < 5; k++) {
        int j = k * PT + t;                 // strip index 0..2303 (24 per row)
        if (j < 2304) {
            int h = j / 24, w = 4 * (j % 24);

            float R[3][6];
            bool wl = w > 0, wr = w < WW - 4;
#pragma unroll
            for (int r = 0; r < 3; r++) {
                int hr = h - 1 + r;
                if (hr >= 0 && hr < HH) {
                    const float* rowp = sy + hr * WW;
                    float4 m = *(const float4*)(rowp + w);
                    R[r][1] = m.x; R[r][2] = m.y; R[r][3] = m.z; R[r][4] = m.w;
                    R[r][0] = wl ? rowp[w - 1] : 0.f;
                    R[r][5] = wr ? rowp[w + 4] : 0.f;
                } else {
#pragma unroll
                    for (int q = 0; q < 6; q++) R[r][q] = 0.f;
                }
            }
            float yc[4], dog[4];
#pragma unroll
            for (int px = 0; px < 4; px++) {
                yc[px] = R[1][px + 1];
                dog[px] = dC * R[1][px+1]
                        + dE * (R[0][px+1] + R[2][px+1] + R[1][px] + R[1][px+2])
                        + dX * (R[0][px] + R[0][px+2] + R[2][px] + R[2][px+2]);
            }

            float e0[4], e1[4], e2[4];
            edge_scale<S0, 3, 1, 0,0,1,1>(p0, h, w, 0.25f,
                0.625f, 0.875f, 0.125f, 0.375f, yc, e0);
            edge_scale<S1, 4, 2, 0,1,1,2>(p1, h, w, 0.5f,
                0.75f, 0.25f, 0.75f, 0.25f, yc, e1);
            edge_scale<S2, 5, 3, 0,1,2,3>(p2, h, w, 0.75f,
                0.875f, 0.625f, 0.375f, 0.125f, yc, e2);

            uint32_t hp[2];
#pragma unroll
            for (int half = 0; half < 2; half++) {
                float v[2];
#pragma unroll
                for (int q = 0; q < 2; q++) {
                    int px = half * 2 + q;
                    float a01 = fabsf(e0[px] - e1[px]);
                    float a02 = fabsf(e0[px] - e2[px]);
                    float a12 = fabsf(e1[px] - e2[px]);
                    float we = (a01 + a02 + a12) * (1.f/3.f);
                    v[q] = 3.f*yc[px] + wf*we + dog[px];
                }
                __half h0 = __float2half_rn(v[0]);
                __half h1 = __float2half_rn(v[1]);
                hp[half] = ((uint32_t)__half_as_ushort(h1) << 16)
                         |  (uint32_t)__half_as_ushort(h0);
            }
            zq4[j] = make_uint2(hp[0], hp[1]);
        }
    }
}

// ===========================================================================
// K4: HMMA asymmetric fp16 GEMM: out = (Wh + Wl)·Zq / 16 + skip
//   CTA 128x128, K=256 in 8 chunks of 32, double-buffered cp.async.
//   8 warps (2M x 4N), warp tile 64x32, 2 products (hi·z, lo·z).
// SMEM per buffer: A hi/lo: 2 x 128 rows x 80B = 20480; B: 32 x 256B = 8192
// ===========================================================================
#define ABUF_SZ 10240
#define BUF_STRIDE 28672            // 2*10240 + 8192
#define GEMM_SMEM (2*BUF_STRIDE)    // 57344

__global__ void __launch_bounds__(256, 2) k_gemm_mma(
        const float* __restrict__ skip, float* __restrict__ out) {
    extern __shared__ char smem_raw[];
    uint32_t sb = smem_u32(smem_raw);

    int t = threadIdx.x, wid = t >> 5, lane = t & 31;
    int wm = wid & 1, wn = wid >> 1;
    int b = blockIdx.z, co0 = blockIdx.y * 128, n0 = blockIdx.x * 128;

    const __half* whlo[2] = { g_wh, g_wl };

    auto load_chunk = [&](int kc, int d) {
        uint32_t base = sb + d * BUF_STRIDE;
#pragma unroll
        for (int j = 0; j < 4; j++) {            // A: 1024 x 16B
            int idx = j * 256 + t;
            int hl = idx >> 9, rem = idx & 511;
            int row = rem >> 2, c = rem & 3;
            const __half* src = whlo[hl] + (co0 + row) * CC + kc * 32 + c * 8;
            CP16(base + hl * ABUF_SZ + row * 80 + c * 16, src);
        }
#pragma unroll
        for (int j = 0; j < 2; j++) {            // B: 512 x 16B
            int idx = j * 256 + t;
            int row = idx >> 4, c = idx & 15;
            const __half* src = g_zq
                + (size_t)(b * CC + kc * 32 + row) * HWP + n0 + c * 8;
            CP16(base + 2 * ABUF_SZ + row * 256
                 + (uint32_t)((c ^ (row & 7)) << 4), src);
        }
    };

    float acc[4][4][4];
#pragma unroll
    for (int i = 0; i < 4; i++)
#pragma unroll
        for (int j = 0; j < 4; j++)
#pragma unroll
            for (int k = 0; k < 4; k++) acc[i][j][k] = 0.f;

    int lt = lane >> 3;
    int lrA = (lane & 7) + ((lt & 1) << 3);
    int lcA = (lt >> 1) << 4;
    int lkB = (lane & 7) + ((lt & 1) << 3);
    int lnB = (lt >> 1) << 3;

    load_chunk(0, 0);
    CP_COMMIT();

    for (int kc = 0; kc < 8; kc++) {
        int d = kc & 1;
        if (kc + 1 < 8) { load_chunk(kc + 1, d ^ 1); CP_COMMIT(); CP_WAIT1(); }
        else           { CP_WAIT0(); }
        __syncthreads();

        uint32_t abase = sb + d * BUF_STRIDE;
        uint32_t bbase = abase + 2 * ABUF_SZ;

#pragma unroll
        for (int ks = 0; ks < 2; ks++) {
            uint32_t ah[4][4], al[4][4];
#pragma unroll
            for (int mi = 0; mi < 4; mi++) {
                uint32_t arow = (uint32_t)(wm * 64 + mi * 16 + lrA);
                ldsm_x4(ah[mi], abase + arow * 80 + ks * 32 + lcA);
                ldsm_x4(al[mi], abase + ABUF_SZ + arow * 80 + ks * 32 + lcA);
            }
#pragma unroll
            for (int np = 0; np < 2; np++) {
                uint32_t krow = (uint32_t)(ks * 16 + lkB);
                uint32_t nb   = (uint32_t)(wn * 32 + np * 16 + lnB);
                uint32_t chunk = nb >> 3;
                uint32_t swz = (chunk ^ (krow & 7)) << 4;
                uint32_t bh[4];
                ldsm_x4_t(bh, bbase + krow * 256 + swz);
#pragma unroll
                for (int mi = 0; mi < 4; mi++) {
                    mma_fp16(acc[mi][np*2+0], ah[mi], bh + 0);
                    mma_fp16(acc[mi][np*2+1], ah[mi], bh + 2);
                    mma_fp16(acc[mi][np*2+0], al[mi], bh + 0);
                    mma_fp16(acc[mi][np*2+1], al[mi], bh + 2);
                }
            }
        }
        __syncthreads();
    }

    // epilogue: descale (1/16 exact) + skip residual
    int er = lane >> 2, ec = (lane & 3) * 2;
    const float ds = 0.0625f;
#pragma unroll
    for (int mi = 0; mi < 4; mi++) {
#pragma unroll
        for (int ni = 0; ni < 4; ni++) {
            int row = co0 + wm * 64 + mi * 16 + er;
            int col = n0 + wn * 32 + ni * 8 + ec;
            size_t g0 = (size_t)(b * CC + row) * HWP + col;
            size_t g1 = g0 + 8 * HWP;
            float2 s0 = *(const float2*)(skip + g0);
            float2 s1 = *(const float2*)(skip + g1);
            float2 o0 = make_float2(acc[mi][ni][0] * ds + s0.x,
                                    acc[mi][ni][1] * ds + s0.y);
            float2 o1 = make_float2(acc[mi][ni][2] * ds + s1.x,
                                    acc[mi][ni][3] * ds + s1.y);
            *(float2*)(out + g0) = o0;
            *(float2*)(out + g1) = o1;
        }
    }
}

// ===========================================================================
// Launch: sequential (overlap experiments R12/R13 regressed)
// ===========================================================================
extern "C" void kernel_launch(void* const* d_in, const int* in_sizes, int n_in,
                              void* d_out, int out_size) {
    const float* skip   = (const float*)d_in[0];
    const float* dec    = (const float*)d_in[1];
    const float* w_fea  = (const float*)d_in[2];
    const float* sigma1 = (const float*)d_in[3];
    const float* sigma2 = (const float*)d_in[4];
    const float* mixerw = (const float*)d_in[5];
    float* out = (float*)d_out;

    k_wsplit<<<CC*CC/256, 256>>>(mixerw);

    cudaFuncSetAttribute(k_plane, cudaFuncAttributeMaxDynamicSharedMemorySize,
                         PLANE_SMEM);
    k_plane<<<BB*CC, PT, PLANE_SMEM>>>((const float4*)dec, (const float4*)skip,
                                       w_fea, sigma1, sigma2);

    cudaFuncSetAttribute(k_gemm_mma, cudaFuncAttributeMaxDynamicSharedMemorySize,
                         GEMM_SMEM);
    dim3 grid(HWP / 128, CC / 128, BB);
    k_gemm_mma<<<grid, 256, GEMM_SMEM>>>(skip, out);
}

// round 16
// speedup vs baseline: 1.5205x; 1.1145x over previous
#include <cuda_runtime.h>
#include <cuda_fp16.h>
#include <math.h>
#include <stdint.h>

// ---- problem constants ----
#define BB 16
#define CC 256
#define HH 96
#define WW 96
#define HWP (HH*WW)                 // 9216
#define NELEM (BB*CC*HWP)           // 37748736
#define S0 24
#define S1 48
#define S2 72

// ---- scratch (device globals: allocation-free rule) ----
__device__ __half g_zq[NELEM];       // z quantized to fp16
__device__ __half g_wq[CC*CC];       // W quantized to fp16

// ===========================================================================
// PTX helpers
// ===========================================================================
__device__ __forceinline__ uint32_t smem_u32(const void* p) {
    uint32_t a;
    asm("{ .reg .u64 t; cvta.to.shared.u64 t, %1; cvt.u32.u64 %0, t; }"
        : "=r"(a) : "l"(p));
    return a;
}
#define CP16(dst, src) asm volatile( \
    "cp.async.cg.shared.global [%0], [%1], 16;" :: "r"(dst), "l"(src) : "memory")
#define CP_COMMIT() asm volatile("cp.async.commit_group;" ::: "memory")
#define CP_WAIT1() asm volatile("cp.async.wait_group 1;" ::: "memory")
#define CP_WAIT0() asm volatile("cp.async.wait_group 0;" ::: "memory")

__device__ __forceinline__ void ldsm_x4(uint32_t* r, uint32_t addr) {
    asm volatile("ldmatrix.sync.aligned.m8n8.x4.shared.b16 {%0,%1,%2,%3}, [%4];"
                 : "=r"(r[0]), "=r"(r[1]), "=r"(r[2]), "=r"(r[3]) : "r"(addr));
}
__device__ __forceinline__ void ldsm_x4_t(uint32_t* r, uint32_t addr) {
    asm volatile("ldmatrix.sync.aligned.m8n8.x4.trans.shared.b16 {%0,%1,%2,%3}, [%4];"
                 : "=r"(r[0]), "=r"(r[1]), "=r"(r[2]), "=r"(r[3]) : "r"(addr));
}
__device__ __forceinline__ void mma_fp16(float* c, const uint32_t* a, const uint32_t* b) {
    asm volatile(
        "mma.sync.aligned.m16n8k16.row.col.f32.f16.f16.f32 "
        "{%0,%1,%2,%3}, {%4,%5,%6,%7}, {%8,%9}, {%0,%1,%2,%3};"
        : "+f"(c[0]), "+f"(c[1]), "+f"(c[2]), "+f"(c[3])
        : "r"(a[0]), "r"(a[1]), "r"(a[2]), "r"(a[3]), "r"(b[0]), "r"(b[1]));
}

// ===========================================================================
// K0: quantize W to fp16
// ===========================================================================
__global__ void k_wsplit(const float* __restrict__ w) {
    int i = blockIdx.x * 256 + threadIdx.x;
    g_wq[i] = __float2half_rn(w[i]);
}

// ===========================================================================
// edge_scale: upsample-edge for one scale over a 4-pixel strip (w%4==0).
// ===========================================================================
template<int S, int NT, int KSM, int XI0, int XI1, int XI2, int XI3>
__device__ __forceinline__ void edge_scale(
        const float* __restrict__ p, int h, int w, float scl,
        float wx0, float wx1, float wx2, float wx3,
        const float* __restrict__ yc, float* __restrict__ eout) {
    float fy = fmaxf((h + 0.5f) * scl - 0.5f, 0.f);
    int y0 = (int)fy;
    float wy = fy - (float)y0;
    const float* pr0 = p + y0 * S;
    const float* pr1 = p + min(y0 + 1, S - 1) * S;
    int x0 = (w >> 2) * KSM - 1;
    float T0[NT], T1[NT];
#pragma unroll
    for (int q = 0; q < NT; q++) {
        int cq = min(max(x0 + q, 0), S - 1);
        T0[q] = pr0[cq];
        T1[q] = pr1[cq];
    }
    const int xiv[4] = { XI0, XI1, XI2, XI3 };
    const float wxv[4] = { wx0, wx1, wx2, wx3 };
#pragma unroll
    for (int px = 0; px < 4; px++) {
        const int xi = xiv[px];
        float wx = wxv[px];
        float top = T0[xi] + (T0[xi+1] - T0[xi]) * wx;
        float bot = T1[xi] + (T1[xi+1] - T1[xi]) * wx;
        float up = top + (bot - top) * wy;
        eout[px] = fabsf(yc[px] - up);
    }
}

// ===========================================================================
// K1: fused per-plane elementwise chain. One CTA / (b,c) plane, 512 threads.
// ===========================================================================
#define SMF_Y  0
#define SMF_D0 9216
#define SMF_D1 (9216+576)
#define SMF_D2 (9216+2880)
#define PLANE_SMEM ((9216+8064)*4)   // 69120 B dynamic
#define PT 512

__device__ __forceinline__ void ds_coord_s2(int o, int& i0, float& w) {
    int m = o / 3, r = o - 3 * m;
    i0 = 4 * m + r;
    w = (r == 0) ? (1.f/6.f) : (r == 1) ? 0.5f : (5.f/6.f);
}

__global__ void __launch_bounds__(PT) k_plane(const float4* __restrict__ dec,
                                              const float4* __restrict__ skip,
                                              const float* __restrict__ wfea,
                                              const float* __restrict__ s1r,
                                              const float* __restrict__ s2r) {
    extern __shared__ float sm[];
    __shared__ float s_dog[3];

    int bc = blockIdx.x;
    int c  = bc % CC;
    int t  = threadIdx.x;

    // 0) DoG difference-kernel coefficients for this channel
    if (t == 0) {
        float s1 = 2.f / (1.f + expf(-s1r[c]));
        float s2 = 2.f / (1.f + expf(-s2r[c]));
        float e1 = expf(-1.f / (2.f * s1 * s1)); float q1 = expf(-1.f / (s1 * s1));
        float e2 = expf(-1.f / (2.f * s2 * s2)); float q2 = expf(-1.f / (s2 * s2));
        float n1 = 1.f + 4.f * e1 + 4.f * q1;
        float n2 = 1.f + 4.f * e2 + 4.f * q2;
        s_dog[0] = 1.f/n1 - 1.f/n2;
        s_dog[1] = e1/n1 - e2/n2;
        s_dog[2] = q1/n1 - q2/n2;
    }

    // 1) y = dec + skip into smem
    const float4* dp = dec  + (size_t)bc * (HWP/4);
    const float4* sp = skip + (size_t)bc * (HWP/4);
    float4* y4 = (float4*)(sm + SMF_Y);
#pragma unroll
    for (int k = 0; k < 5; k++) {
        int i = k * PT + t;
        if (i < HWP/4) {
            float4 a = dp[i], b = sp[i];
            y4[i] = make_float4(a.x + b.x, a.y + b.y, a.z + b.z, a.w + b.w);
        }
    }
    __syncthreads();

    const float* sy = sm + SMF_Y;

    // 2) three bilinear downsamples into smem, exact compile-time geometry
#pragma unroll
    for (int k = 0; k < 16; k++) {
        int i = k * PT + t;
        if (i >= 8064) break;
        int y0, x0; float wy, wx;
        int off, o;
        if (i < 576) {
            off = SMF_D0; o = i;
            int oy = o / S0, ox = o - oy * S0;
            y0 = 4 * oy + 1; x0 = 4 * ox + 1; wy = 0.5f; wx = 0.5f;
        } else if (i < 2880) {
            off = SMF_D1; o = i - 576;
            int oy = o / S1, ox = o - oy * S1;
            y0 = 2 * oy; x0 = 2 * ox; wy = 0.5f; wx = 0.5f;
        } else {
            off = SMF_D2; o = i - 2880;
            int oy = o / S2, ox = o - oy * S2;
            ds_coord_s2(oy, y0, wy);
            ds_coord_s2(ox, x0, wx);
        }
        const float* r0p = sy + y0 * WW;
        const float* r1p = sy + (y0 + 1) * WW;   // never clamps (max y0 = 94)
        float v00 = r0p[x0], v01 = r0p[x0 + 1];
        float v10 = r1p[x0], v11 = r1p[x0 + 1];
        sm[off + o] = (v00*(1.f-wx) + v01*wx)*(1.f-wy) + (v10*(1.f-wx) + v11*wx)*wy;
    }
    __syncthreads();

    // 3) fused edges + DoG + combine -> zq (fp16): 4-pixel strips
    float dC = s_dog[0], dE = s_dog[1], dX = s_dog[2];
    float wf = wfea[c];
    const float* p0 = sm + SMF_D0;
    const float* p1 = sm + SMF_D1;
    const float* p2 = sm + SMF_D2;
    size_t gbase = (size_t)bc * HWP;
    uint2* zq4 = (uint2*)(g_zq + gbase);

#pragma unroll
    for (int k = 0; k < 5; k++) {
        int j = k * PT + t;                 // strip index 0..2303 (24 per row)
        if (j < 2304) {
            int h = j / 24, w = 4 * (j % 24);

            float R[3][6];
            bool wl = w > 0, wr = w < WW - 4;
#pragma unroll
            for (int r = 0; r < 3; r++) {
                int hr = h - 1 + r;
                if (hr >= 0 && hr < HH) {
                    const float* rowp = sy + hr * WW;
                    float4 m = *(const float4*)(rowp + w);
                    R[r][1] = m.x; R[r][2] = m.y; R[r][3] = m.z; R[r][4] = m.w;
                    R[r][0] = wl ? rowp[w - 1] : 0.f;
                    R[r][5] = wr ? rowp[w + 4] : 0.f;
                } else {
#pragma unroll
                    for (int q = 0; q < 6; q++) R[r][q] = 0.f;
                }
            }
            float yc[4], dog[4];
#pragma unroll
            for (int px = 0; px < 4; px++) {
                yc[px] = R[1][px + 1];
                dog[px] = dC * R[1][px+1]
                        + dE * (R[0][px+1] + R[2][px+1] + R[1][px] + R[1][px+2])
                        + dX * (R[0][px] + R[0][px+2] + R[2][px] + R[2][px+2]);
            }

            float e0[4], e1[4], e2[4];
            edge_scale<S0, 3, 1, 0,0,1,1>(p0, h, w, 0.25f,
                0.625f, 0.875f, 0.125f, 0.375f, yc, e0);
            edge_scale<S1, 4, 2, 0,1,1,2>(p1, h, w, 0.5f,
                0.75f, 0.25f, 0.75f, 0.25f, yc, e1);
            edge_scale<S2, 5, 3, 0,1,2,3>(p2, h, w, 0.75f,
                0.875f, 0.625f, 0.375f, 0.125f, yc, e2);

            uint32_t hp[2];
#pragma unroll
            for (int half = 0; half < 2; half++) {
                float v[2];
#pragma unroll
                for (int q = 0; q < 2; q++) {
                    int px = half * 2 + q;
                    float a01 = fabsf(e0[px] - e1[px]);
                    float a02 = fabsf(e0[px] - e2[px]);
                    float a12 = fabsf(e1[px] - e2[px]);
                    float we = (a01 + a02 + a12) * (1.f/3.f);
                    v[q] = 3.f*yc[px] + wf*we + dog[px];
                }
                __half h0 = __float2half_rn(v[0]);
                __half h1 = __float2half_rn(v[1]);
                hp[half] = ((uint32_t)__half_as_ushort(h1) << 16)
                         |  (uint32_t)__half_as_ushort(h0);
            }
            zq4[j] = make_uint2(hp[0], hp[1]);
        }
    }
}

// ===========================================================================
// K4: plain fp16 HMMA GEMM: out = Wq·Zq + skip
//   CTA 128x128, K=256 in 8 chunks of 32, double-buffered cp.async.
//   8 warps (2M x 4N), warp tile 64x32, single product.
// SMEM per buffer: A: 128 rows x 80B = 10240; B: 32 x 256B = 8192
// ===========================================================================
#define ABUF_SZ 10240
#define BUF_STRIDE 18432            // 10240 + 8192
#define GEMM_SMEM (2*BUF_STRIDE)    // 36864

__global__ void __launch_bounds__(256, 2) k_gemm_mma(
        const float* __restrict__ skip, float* __restrict__ out) {
    extern __shared__ char smem_raw[];
    uint32_t sb = smem_u32(smem_raw);

    int t = threadIdx.x, wid = t >> 5, lane = t & 31;
    int wm = wid & 1, wn = wid >> 1;
    int b = blockIdx.z, co0 = blockIdx.y * 128, n0 = blockIdx.x * 128;

    auto load_chunk = [&](int kc, int d) {
        uint32_t base = sb + d * BUF_STRIDE;
#pragma unroll
        for (int j = 0; j < 2; j++) {            // A: 512 x 16B
            int idx = j * 256 + t;
            int row = idx >> 2, c = idx & 3;
            const __half* src = g_wq + (co0 + row) * CC + kc * 32 + c * 8;
            CP16(base + row * 80 + c * 16, src);
        }
#pragma unroll
        for (int j = 0; j < 2; j++) {            // B: 512 x 16B
            int idx = j * 256 + t;
            int row = idx >> 4, c = idx & 15;
            const __half* src = g_zq
                + (size_t)(b * CC + kc * 32 + row) * HWP + n0 + c * 8;
            CP16(base + ABUF_SZ + row * 256
                 + (uint32_t)((c ^ (row & 7)) << 4), src);
        }
    };

    float acc[4][4][4];
#pragma unroll
    for (int i = 0; i < 4; i++)
#pragma unroll
        for (int j = 0; j < 4; j++)
#pragma unroll
            for (int k = 0; k < 4; k++) acc[i][j][k] = 0.f;

    int lt = lane >> 3;
    int lrA = (lane & 7) + ((lt & 1) << 3);
    int lcA = (lt >> 1) << 4;
    int lkB = (lane & 7) + ((lt & 1) << 3);
    int lnB = (lt >> 1) << 3;

    load_chunk(0, 0);
    CP_COMMIT();

    for (int kc = 0; kc < 8; kc++) {
        int d = kc & 1;
        if (kc + 1 < 8) { load_chunk(kc + 1, d ^ 1); CP_COMMIT(); CP_WAIT1(); }
        else           { CP_WAIT0(); }
        __syncthreads();

        uint32_t abase = sb + d * BUF_STRIDE;
        uint32_t bbase = abase + ABUF_SZ;

#pragma unroll
        for (int ks = 0; ks < 2; ks++) {
            uint32_t ah[4][4];
#pragma unroll
            for (int mi = 0; mi < 4; mi++) {
                uint32_t arow = (uint32_t)(wm * 64 + mi * 16 + lrA);
                ldsm_x4(ah[mi], abase + arow * 80 + ks * 32 + lcA);
            }
#pragma unroll
            for (int np = 0; np < 2; np++) {
                uint32_t krow = (uint32_t)(ks * 16 + lkB);
                uint32_t nb   = (uint32_t)(wn * 32 + np * 16 + lnB);
                uint32_t chunk = nb >> 3;
                uint32_t swz = (chunk ^ (krow & 7)) << 4;
                uint32_t bh[4];
                ldsm_x4_t(bh, bbase + krow * 256 + swz);
#pragma unroll
                for (int mi = 0; mi < 4; mi++) {
                    mma_fp16(acc[mi][np*2+0], ah[mi], bh + 0);
                    mma_fp16(acc[mi][np*2+1], ah[mi], bh + 2);
                }
            }
        }
        __syncthreads();
    }

    int er = lane >> 2, ec = (lane & 3) * 2;
#pragma unroll
    for (int mi = 0; mi < 4; mi++) {
#pragma unroll
        for (int ni = 0; ni < 4; ni++) {
            int row = co0 + wm * 64 + mi * 16 + er;
            int col = n0 + wn * 32 + ni * 8 + ec;
            size_t g0 = (size_t)(b * CC + row) * HWP + col;
            size_t g1 = g0 + 8 * HWP;
            float2 s0 = *(const float2*)(skip + g0);
            float2 s1 = *(const float2*)(skip + g1);
            float2 o0 = make_float2(acc[mi][ni][0] + s0.x, acc[mi][ni][1] + s0.y);
            float2 o1 = make_float2(acc[mi][ni][2] + s1.x, acc[mi][ni][3] + s1.y);
            *(float2*)(out + g0) = o0;
            *(float2*)(out + g1) = o1;
        }
    }
}

// ===========================================================================
// Launch: sequential (overlap experiments R12/R13 regressed)
// ===========================================================================
extern "C" void kernel_launch(void* const* d_in, const int* in_sizes, int n_in,
                              void* d_out, int out_size) {
    const float* skip   = (const float*)d_in[0];
    const float* dec    = (const float*)d_in[1];
    const float* w_fea  = (const float*)d_in[2];
    const float* sigma1 = (const float*)d_in[3];
    const float* sigma2 = (const float*)d_in[4];
    const float* mixerw = (const float*)d_in[5];
    float* out = (float*)d_out;

    k_wsplit<<<CC*CC/256, 256>>>(mixerw);

    cudaFuncSetAttribute(k_plane, cudaFuncAttributeMaxDynamicSharedMemorySize,
                         PLANE_SMEM);
    k_plane<<<BB*CC, PT, PLANE_SMEM>>>((const float4*)dec, (const float4*)skip,
                                       w_fea, sigma1, sigma2);

    cudaFuncSetAttribute(k_gemm_mma, cudaFuncAttributeMaxDynamicSharedMemorySize,
                         GEMM_SMEM);
    dim3 grid(HWP / 128, CC / 128, BB);
    k_gemm_mma<<<grid, 256, GEMM_SMEM>>>(skip, out);
}

// round 17
// speedup vs baseline: 1.5334x; 1.0085x over previous
#include <cuda_runtime.h>
#include <cuda_fp16.h>
#include <math.h>
#include <stdint.h>

// ---- problem constants ----
#define BB 16
#define CC 256
#define HH 96
#define WW 96
#define HWP (HH*WW)                 // 9216
#define NELEM (BB*CC*HWP)           // 37748736
#define S0 24
#define S1 48
#define S2 72

// ---- scratch (device globals: allocation-free rule) ----
__device__ __half g_zq[NELEM];       // z quantized to fp16
__device__ __half g_wq[CC*CC];       // W quantized to fp16

// ===========================================================================
// PTX helpers
// ===========================================================================
__device__ __forceinline__ uint32_t smem_u32(const void* p) {
    uint32_t a;
    asm("{ .reg .u64 t; cvta.to.shared.u64 t, %1; cvt.u32.u64 %0, t; }"
        : "=r"(a) : "l"(p));
    return a;
}
#define CP16(dst, src) asm volatile( \
    "cp.async.cg.shared.global [%0], [%1], 16;" :: "r"(dst), "l"(src) : "memory")
#define CP_COMMIT() asm volatile("cp.async.commit_group;" ::: "memory")
#define CP_WAIT2() asm volatile("cp.async.wait_group 2;" ::: "memory")
#define CP_WAIT1() asm volatile("cp.async.wait_group 1;" ::: "memory")
#define CP_WAIT0() asm volatile("cp.async.wait_group 0;" ::: "memory")

__device__ __forceinline__ void ldsm_x4(uint32_t* r, uint32_t addr) {
    asm volatile("ldmatrix.sync.aligned.m8n8.x4.shared.b16 {%0,%1,%2,%3}, [%4];"
                 : "=r"(r[0]), "=r"(r[1]), "=r"(r[2]), "=r"(r[3]) : "r"(addr));
}
__device__ __forceinline__ void ldsm_x4_t(uint32_t* r, uint32_t addr) {
    asm volatile("ldmatrix.sync.aligned.m8n8.x4.trans.shared.b16 {%0,%1,%2,%3}, [%4];"
                 : "=r"(r[0]), "=r"(r[1]), "=r"(r[2]), "=r"(r[3]) : "r"(addr));
}
__device__ __forceinline__ void mma_fp16(float* c, const uint32_t* a, const uint32_t* b) {
    asm volatile(
        "mma.sync.aligned.m16n8k16.row.col.f32.f16.f16.f32 "
        "{%0,%1,%2,%3}, {%4,%5,%6,%7}, {%8,%9}, {%0,%1,%2,%3};"
        : "+f"(c[0]), "+f"(c[1]), "+f"(c[2]), "+f"(c[3])
        : "r"(a[0]), "r"(a[1]), "r"(a[2]), "r"(a[3]), "r"(b[0]), "r"(b[1]));
}

// ===========================================================================
// K0: quantize W to fp16
// ===========================================================================
__global__ void k_wsplit(const float* __restrict__ w) {
    int i = blockIdx.x * 256 + threadIdx.x;
    g_wq[i] = __float2half_rn(w[i]);
}

// ===========================================================================
// edge_scale: upsample-edge for one scale over a 4-pixel strip (w%4==0).
// ===========================================================================
template<int S, int NT, int KSM, int XI0, int XI1, int XI2, int XI3>
__device__ __forceinline__ void edge_scale(
        const float* __restrict__ p, int h, int w, float scl,
        float wx0, float wx1, float wx2, float wx3,
        const float* __restrict__ yc, float* __restrict__ eout) {
    float fy = fmaxf((h + 0.5f) * scl - 0.5f, 0.f);
    int y0 = (int)fy;
    float wy = fy - (float)y0;
    const float* pr0 = p + y0 * S;
    const float* pr1 = p + min(y0 + 1, S - 1) * S;
    int x0 = (w >> 2) * KSM - 1;
    float T0[NT], T1[NT];
#pragma unroll
    for (int q = 0; q < NT; q++) {
        int cq = min(max(x0 + q, 0), S - 1);
        T0[q] = pr0[cq];
        T1[q] = pr1[cq];
    }
    const int xiv[4] = { XI0, XI1, XI2, XI3 };
    const float wxv[4] = { wx0, wx1, wx2, wx3 };
#pragma unroll
    for (int px = 0; px < 4; px++) {
        const int xi = xiv[px];
        float wx = wxv[px];
        float top = T0[xi] + (T0[xi+1] - T0[xi]) * wx;
        float bot = T1[xi] + (T1[xi+1] - T1[xi]) * wx;
        float up = top + (bot - top) * wy;
        eout[px] = fabsf(yc[px] - up);
    }
}

// ===========================================================================
// K1: fused per-plane elementwise chain. One CTA / (b,c) plane, 512 threads.
// ===========================================================================
#define SMF_Y  0
#define SMF_D0 9216
#define SMF_D1 (9216+576)
#define SMF_D2 (9216+2880)
#define PLANE_SMEM ((9216+8064)*4)   // 69120 B dynamic
#define PT 512

__device__ __forceinline__ void ds_coord_s2(int o, int& i0, float& w) {
    int m = o / 3, r = o - 3 * m;
    i0 = 4 * m + r;
    w = (r == 0) ? (1.f/6.f) : (r == 1) ? 0.5f : (5.f/6.f);
}

__global__ void __launch_bounds__(PT) k_plane(const float4* __restrict__ dec,
                                              const float4* __restrict__ skip,
                                              const float* __restrict__ wfea,
                                              const float* __restrict__ s1r,
                                              const float* __restrict__ s2r) {
    extern __shared__ float sm[];
    __shared__ float s_dog[3];

    int bc = blockIdx.x;
    int c  = bc % CC;
    int t  = threadIdx.x;

    if (t == 0) {
        float s1 = 2.f / (1.f + expf(-s1r[c]));
        float s2 = 2.f / (1.f + expf(-s2r[c]));
        float e1 = expf(-1.f / (2.f * s1 * s1)); float q1 = expf(-1.f / (s1 * s1));
        float e2 = expf(-1.f / (2.f * s2 * s2)); float q2 = expf(-1.f / (s2 * s2));
        float n1 = 1.f + 4.f * e1 + 4.f * q1;
        float n2 = 1.f + 4.f * e2 + 4.f * q2;
        s_dog[0] = 1.f/n1 - 1.f/n2;
        s_dog[1] = e1/n1 - e2/n2;
        s_dog[2] = q1/n1 - q2/n2;
    }

    const float4* dp = dec  + (size_t)bc * (HWP/4);
    const float4* sp = skip + (size_t)bc * (HWP/4);
    float4* y4 = (float4*)(sm + SMF_Y);
#pragma unroll
    for (int k = 0; k < 5; k++) {
        int i = k * PT + t;
        if (i < HWP/4) {
            float4 a = dp[i], b = sp[i];
            y4[i] = make_float4(a.x + b.x, a.y + b.y, a.z + b.z, a.w + b.w);
        }
    }
    __syncthreads();

    const float* sy = sm + SMF_Y;

#pragma unroll
    for (int k = 0; k < 16; k++) {
        int i = k * PT + t;
        if (i >= 8064) break;
        int y0, x0; float wy, wx;
        int off, o;
        if (i < 576) {
            off = SMF_D0; o = i;
            int oy = o / S0, ox = o - oy * S0;
            y0 = 4 * oy + 1; x0 = 4 * ox + 1; wy = 0.5f; wx = 0.5f;
        } else if (i < 2880) {
            off = SMF_D1; o = i - 576;
            int oy = o / S1, ox = o - oy * S1;
            y0 = 2 * oy; x0 = 2 * ox; wy = 0.5f; wx = 0.5f;
        } else {
            off = SMF_D2; o = i - 2880;
            int oy = o / S2, ox = o - oy * S2;
            ds_coord_s2(oy, y0, wy);
            ds_coord_s2(ox, x0, wx);
        }
        const float* r0p = sy + y0 * WW;
        const float* r1p = sy + (y0 + 1) * WW;
        float v00 = r0p[x0], v01 = r0p[x0 + 1];
        float v10 = r1p[x0], v11 = r1p[x0 + 1];
        sm[off + o] = (v00*(1.f-wx) + v01*wx)*(1.f-wy) + (v10*(1.f-wx) + v11*wx)*wy;
    }
    __syncthreads();

    float dC = s_dog[0], dE = s_dog[1], dX = s_dog[2];
    float wf = wfea[c];
    const float* p0 = sm + SMF_D0;
    const float* p1 = sm + SMF_D1;
    const float* p2 = sm + SMF_D2;
    size_t gbase = (size_t)bc * HWP;
    uint2* zq4 = (uint2*)(g_zq + gbase);

#pragma unroll
    for (int k = 0; k < 5; k++) {
        int j = k * PT + t;
        if (j < 2304) {
            int h = j / 24, w = 4 * (j % 24);

            float R[3][6];
            bool wl = w > 0, wr = w < WW - 4;
#pragma unroll
            for (int r = 0; r < 3; r++) {
                int hr = h - 1 + r;
                if (hr >= 0 && hr < HH) {
                    const float* rowp = sy + hr * WW;
                    float4 m = *(const float4*)(rowp + w);
                    R[r][1] = m.x; R[r][2] = m.y; R[r][3] = m.z; R[r][4] = m.w;
                    R[r][0] = wl ? rowp[w - 1] : 0.f;
                    R[r][5] = wr ? rowp[w + 4] : 0.f;
                } else {
#pragma unroll
                    for (int q = 0; q < 6; q++) R[r][q] = 0.f;
                }
            }
            float yc[4], dog[4];
#pragma unroll
            for (int px = 0; px < 4; px++) {
                yc[px] = R[1][px + 1];
                dog[px] = dC * R[1][px+1]
                        + dE * (R[0][px+1] + R[2][px+1] + R[1][px] + R[1][px+2])
                        + dX * (R[0][px] + R[0][px+2] + R[2][px] + R[2][px+2]);
            }

            float e0[4], e1[4], e2[4];
            edge_scale<S0, 3, 1, 0,0,1,1>(p0, h, w, 0.25f,
                0.625f, 0.875f, 0.125f, 0.375f, yc, e0);
            edge_scale<S1, 4, 2, 0,1,1,2>(p1, h, w, 0.5f,
                0.75f, 0.25f, 0.75f, 0.25f, yc, e1);
            edge_scale<S2, 5, 3, 0,1,2,3>(p2, h, w, 0.75f,
                0.875f, 0.625f, 0.375f, 0.125f, yc, e2);

            uint32_t hp[2];
#pragma unroll
            for (int half = 0; half < 2; half++) {
                float v[2];
#pragma unroll
                for (int q = 0; q < 2; q++) {
                    int px = half * 2 + q;
                    float a01 = fabsf(e0[px] - e1[px]);
                    float a02 = fabsf(e0[px] - e2[px]);
                    float a12 = fabsf(e1[px] - e2[px]);
                    float we = (a01 + a02 + a12) * (1.f/3.f);
                    v[q] = 3.f*yc[px] + wf*we + dog[px];
                }
                __half h0 = __float2half_rn(v[0]);
                __half h1 = __float2half_rn(v[1]);
                hp[half] = ((uint32_t)__half_as_ushort(h1) << 16)
                         |  (uint32_t)__half_as_ushort(h0);
            }
            zq4[j] = make_uint2(hp[0], hp[1]);
        }
    }
}

// ===========================================================================
// K4: plain fp16 HMMA GEMM, 4-stage cp.async pipeline.
//   CTA 128x128, K=256 in 8 chunks of 32; grid (co, n, b) so the two
//   co-blocks sharing a B tile are schedule-adjacent (L2 reuse).
// ===========================================================================
#define ABUF_SZ 10240
#define BUF_STRIDE 18432            // 10240 + 8192
#define NSTAGE 4
#define GEMM_SMEM (NSTAGE*BUF_STRIDE)  // 73728

__global__ void __launch_bounds__(256, 2) k_gemm_mma(
        const float* __restrict__ skip, float* __restrict__ out) {
    extern __shared__ char smem_raw[];
    uint32_t sb = smem_u32(smem_raw);

    int t = threadIdx.x, wid = t >> 5, lane = t & 31;
    int wm = wid & 1, wn = wid >> 1;
    int b = blockIdx.z, co0 = blockIdx.x * 128, n0 = blockIdx.y * 128;

    auto load_chunk = [&](int kc, int d) {
        uint32_t base = sb + (uint32_t)d * BUF_STRIDE;
#pragma unroll
        for (int j = 0; j < 2; j++) {            // A: 512 x 16B
            int idx = j * 256 + t;
            int row = idx >> 2, c = idx & 3;
            const __half* src = g_wq + (co0 + row) * CC + kc * 32 + c * 8;
            CP16(base + row * 80 + c * 16, src);
        }
#pragma unroll
        for (int j = 0; j < 2; j++) {            // B: 512 x 16B
            int idx = j * 256 + t;
            int row = idx >> 4, c = idx & 15;
            const __half* src = g_zq
                + (size_t)(b * CC + kc * 32 + row) * HWP + n0 + c * 8;
            CP16(base + ABUF_SZ + row * 256
                 + (uint32_t)((c ^ (row & 7)) << 4), src);
        }
    };

    float acc[4][4][4];
#pragma unroll
    for (int i = 0; i < 4; i++)
#pragma unroll
        for (int j = 0; j < 4; j++)
#pragma unroll
            for (int k = 0; k < 4; k++) acc[i][j][k] = 0.f;

    int lt = lane >> 3;
    int lrA = (lane & 7) + ((lt & 1) << 3);
    int lcA = (lt >> 1) << 4;
    int lkB = (lane & 7) + ((lt & 1) << 3);
    int lnB = (lt >> 1) << 3;

    // prologue: 3 chunks in flight
    load_chunk(0, 0); CP_COMMIT();
    load_chunk(1, 1); CP_COMMIT();
    load_chunk(2, 2); CP_COMMIT();

    for (int kc = 0; kc < 8; kc++) {
        if (kc <= 5)      CP_WAIT2();
        else if (kc == 6) CP_WAIT1();
        else              CP_WAIT0();
        __syncthreads();
        if (kc + 3 < 8) { load_chunk(kc + 3, (kc + 3) & 3); CP_COMMIT(); }

        uint32_t abase = sb + (uint32_t)(kc & 3) * BUF_STRIDE;
        uint32_t bbase = abase + ABUF_SZ;

#pragma unroll
        for (int ks = 0; ks < 2; ks++) {
            uint32_t ah[4][4];
#pragma unroll
            for (int mi = 0; mi < 4; mi++) {
                uint32_t arow = (uint32_t)(wm * 64 + mi * 16 + lrA);
                ldsm_x4(ah[mi], abase + arow * 80 + ks * 32 + lcA);
            }
#pragma unroll
            for (int np = 0; np < 2; np++) {
                uint32_t krow = (uint32_t)(ks * 16 + lkB);
                uint32_t nb   = (uint32_t)(wn * 32 + np * 16 + lnB);
                uint32_t chunk = nb >> 3;
                uint32_t swz = (chunk ^ (krow & 7)) << 4;
                uint32_t bh[4];
                ldsm_x4_t(bh, bbase + krow * 256 + swz);
#pragma unroll
                for (int mi = 0; mi < 4; mi++) {
                    mma_fp16(acc[mi][np*2+0], ah[mi], bh + 0);
                    mma_fp16(acc[mi][np*2+1], ah[mi], bh + 2);
                }
            }
        }
    }

    int er = lane >> 2, ec = (lane & 3) * 2;
#pragma unroll
    for (int mi = 0; mi < 4; mi++) {
#pragma unroll
        for (int ni = 0; ni < 4; ni++) {
            int row = co0 + wm * 64 + mi * 16 + er;
            int col = n0 + wn * 32 + ni * 8 + ec;
            size_t g0 = (size_t)(b * CC + row) * HWP + col;
            size_t g1 = g0 + 8 * HWP;
            float2 s0 = *(const float2*)(skip + g0);
            float2 s1 = *(const float2*)(skip + g1);
            float2 o0 = make_float2(acc[mi][ni][0] + s0.x, acc[mi][ni][1] + s0.y);
            float2 o1 = make_float2(acc[mi][ni][2] + s1.x, acc[mi][ni][3] + s1.y);
            *(float2*)(out + g0) = o0;
            *(float2*)(out + g1) = o1;
        }
    }
}

// ===========================================================================
// Launch: sequential (overlap experiments R12/R13 regressed)
// ===========================================================================
extern "C" void kernel_launch(void* const* d_in, const int* in_sizes, int n_in,
                              void* d_out, int out_size) {
    const float* skip   = (const float*)d_in[0];
    const float* dec    = (const float*)d_in[1];
    const float* w_fea  = (const float*)d_in[2];
    const float* sigma1 = (const float*)d_in[3];
    const float* sigma2 = (const float*)d_in[4];
    const float* mixerw = (const float*)d_in[5];
    float* out = (float*)d_out;

    k_wsplit<<<CC*CC/256, 256>>>(mixerw);

    cudaFuncSetAttribute(k_plane, cudaFuncAttributeMaxDynamicSharedMemorySize,
                         PLANE_SMEM);
    k_plane<<<BB*CC, PT, PLANE_SMEM>>>((const float4*)dec, (const float4*)skip,
                                       w_fea, sigma1, sigma2);

    cudaFuncSetAttribute(k_gemm_mma, cudaFuncAttributeMaxDynamicSharedMemorySize,
                         GEMM_SMEM);
    dim3 grid(CC / 128, HWP / 128, BB);
    k_gemm_mma<<<grid, 256, GEMM_SMEM>>>(skip, out);
}